// round 2
// baseline (speedup 1.0000x reference)
#include <cuda_runtime.h>
#include <cstdint>

#define BATCH 256
#define DIM   2048
#define PNUM  56
#define NROWS (PNUM * BATCH)          // 14336
#define D4    (DIM / 4)               // 512 float4 per row

// log2(e)/T  with T=4
#define KEXP  0.3606737602222409f

// --- device scratch (no allocs allowed) ---
__device__ double       g_acc[2];             // [0]=soft_dil, [1]=soft_dcl (double accum)
__device__ unsigned int g_ctr;                // work counter for dcl
__device__ float        g_mean[BATCH * DIM];  // ebp_bar

__device__ __forceinline__ float ex2f(float x) {
    float r;
    asm("ex2.approx.ftz.f32 %0, %1;" : "=f"(r) : "f"(x));
    return r;
}

__global__ void k_init() {
    if (threadIdx.x < 2) g_acc[threadIdx.x] = 0.0;
    if (threadIdx.x == 0) g_ctr = 0u;
}

// Fused: ebp_bar[b,:] = mean_p ebp[p,b,:]  AND  soft_dil contribution for row b.
// One block per b, 512 threads, each thread owns one float4 of the row.
__global__ void __launch_bounds__(512) k_mean_dil(const float* __restrict__ ebp,
                                                  const float* __restrict__ ebg) {
    __shared__ float red[16 * 4];
    int b  = blockIdx.x;
    int d4 = threadIdx.x;                      // 0..511
    const float4* e4 = (const float4*)ebp;

    float sx = 0.f, sy = 0.f, sz = 0.f, sw = 0.f;
#pragma unroll 8
    for (int p = 0; p < PNUM; p++) {
        float4 v = e4[(p * BATCH + b) * D4 + d4];
        sx += v.x; sy += v.y; sz += v.z; sw += v.w;
    }
    const float inv = 1.0f / (float)PNUM;
    float4 m; m.x = sx * inv; m.y = sy * inv; m.z = sz * inv; m.w = sw * inv;
    ((float4*)g_mean)[b * D4 + d4] = m;

    // dil sums: E_m[u] - E_g[u], u = m - g
    float4 g = ((const float4*)(ebg + (size_t)b * DIM))[d4];
    float se_g = 0.f, se_m = 0.f, su_g = 0.f, su_m = 0.f;
#define DIL1(c) { float u = m.c - g.c;                      \
                  float eg = ex2f(g.c * KEXP);              \
                  float em = ex2f(m.c * KEXP);              \
                  se_g += eg; se_m += em;                   \
                  su_g = fmaf(eg, u, su_g);                 \
                  su_m = fmaf(em, u, su_m); }
    DIL1(x) DIL1(y) DIL1(z) DIL1(w)
#undef DIL1

    int lane = threadIdx.x & 31, warp = threadIdx.x >> 5;
#pragma unroll
    for (int off = 16; off; off >>= 1) {
        se_g += __shfl_xor_sync(0xffffffffu, se_g, off);
        se_m += __shfl_xor_sync(0xffffffffu, se_m, off);
        su_g += __shfl_xor_sync(0xffffffffu, su_g, off);
        su_m += __shfl_xor_sync(0xffffffffu, su_m, off);
    }
    if (lane == 0) {
        red[warp]      = se_g; red[warp + 16] = se_m;
        red[warp + 32] = su_g; red[warp + 48] = su_m;
    }
    __syncthreads();
    if (warp == 0) {
        float a = (lane < 16) ? red[lane]      : 0.f;
        float c = (lane < 16) ? red[lane + 16] : 0.f;
        float d = (lane < 16) ? red[lane + 32] : 0.f;
        float e = (lane < 16) ? red[lane + 48] : 0.f;
#pragma unroll
        for (int off = 8; off; off >>= 1) {
            a += __shfl_xor_sync(0xffffffffu, a, off);
            c += __shfl_xor_sync(0xffffffffu, c, off);
            d += __shfl_xor_sync(0xffffffffu, d, off);
            e += __shfl_xor_sync(0xffffffffu, e, off);
        }
        if (lane == 0) {
            float kl = e / c - d / a;       // E_m[u] - E_g[u]
            atomicAdd(&g_acc[0], (double)kl * (4.0 / (double)DIM));
        }
    }
}

// soft_dcl: warp-per-row work stealing; row index == ebp row (item = p*B+b)
//   u = db^2 - dg^2 = (db-dg)(db+dg); contribution (T/D)*(E_y[u] - E_x[u]), /P
__global__ void __launch_bounds__(256, 8) k_dcl(const float* __restrict__ ebg,
                                                const float* __restrict__ ebp) {
    int lane = threadIdx.x & 31;
    float local = 0.f;

    unsigned item = 0;
    if (lane == 0) item = atomicAdd(&g_ctr, 1u);
    item = __shfl_sync(0xffffffffu, item, 0);

    while (item < NROWS) {
        int b = (int)(item & (BATCH - 1));
        const float4* p4 = (const float4*)(ebp    + (size_t)item * DIM) + lane;
        const float4* g4 = (const float4*)(ebg    + (size_t)b    * DIM) + lane;
        const float4* m4 = (const float4*)(g_mean + (size_t)b    * DIM) + lane;

        float se_x = 0.f, se_y = 0.f, su_x = 0.f, su_y = 0.f;
#pragma unroll 4
        for (int i = 0; i < 16; i++) {
            float4 p = p4[i * 32];
            float4 g = g4[i * 32];
            float4 m = m4[i * 32];
#define DCL1(c) { float dg = g.c - p.c;                         \
                  float db = m.c - p.c;                         \
                  float u  = (db - dg) * (db + dg);             \
                  float ex = ex2f(dg * dg * KEXP);              \
                  float ey = ex2f(db * db * KEXP);              \
                  se_x += ex; se_y += ey;                       \
                  su_x = fmaf(ex, u, su_x);                     \
                  su_y = fmaf(ey, u, su_y); }
            DCL1(x) DCL1(y) DCL1(z) DCL1(w)
#undef DCL1
        }
#pragma unroll
        for (int off = 16; off; off >>= 1) {
            se_x += __shfl_xor_sync(0xffffffffu, se_x, off);
            se_y += __shfl_xor_sync(0xffffffffu, se_y, off);
            su_x += __shfl_xor_sync(0xffffffffu, su_x, off);
            su_y += __shfl_xor_sync(0xffffffffu, su_y, off);
        }
        local += su_y / se_y - su_x / se_x;

        if (lane == 0) item = atomicAdd(&g_ctr, 1u);
        item = __shfl_sync(0xffffffffu, item, 0);
    }
    if (lane == 0)
        atomicAdd(&g_acc[1], (double)local * (4.0 / ((double)DIM * (double)PNUM)));
}

__global__ void k_fin(float* __restrict__ out) {
    if (threadIdx.x == 0) {
        out[0] = (float)g_acc[0];
        out[1] = (float)g_acc[1];
    }
}

extern "C" void kernel_launch(void* const* d_in, const int* in_sizes, int n_in,
                              void* d_out, int out_size) {
    const float* ebg = (const float*)d_in[0];
    const float* ebp = (const float*)d_in[1];
    (void)in_sizes; (void)n_in;

    k_init<<<1, 32>>>();
    k_mean_dil<<<BATCH, 512>>>(ebp, ebg);      // mean + dil fused, block per b
    k_dcl<<<148 * 8, 256>>>(ebg, ebp);         // 2048 thr/SM, warp-per-row stealing
    k_fin<<<1, 32>>>((float*)d_out);
}

// round 3
// speedup vs baseline: 1.0753x; 1.0753x over previous
#include <cuda_runtime.h>
#include <cstdint>

#define BATCH 256
#define DIM   2048
#define PNUM  56
#define NROWS (PNUM * BATCH)          // 14336
#define D4    (DIM / 4)               // 512 float4 per row
#define D2U   (DIM / 4)               // ulonglong2 per row = 512 as well
#define GRID2 888

// log2(e)/T with T=4
#define KEXP  0.3606737602222409f

typedef unsigned long long u64;

// --- device scratch ---
__device__ double       g_acc1;               // dcl accumulator
__device__ unsigned int g_ctr;                // work counter for dcl
__device__ unsigned int g_done;               // finished-block counter for dcl
__device__ float        g_mean[BATCH * DIM];  // ebp_bar
__device__ float        g_dil4[512][4];       // per (b,half): se_g, se_m, su_g, su_m

__device__ __forceinline__ float ex2f(float x) {
    float r; asm("ex2.approx.ftz.f32 %0, %1;" : "=f"(r) : "f"(x)); return r;
}
__device__ __forceinline__ u64 f2_add(u64 a, u64 b) {
    u64 r; asm("add.rn.f32x2 %0, %1, %2;" : "=l"(r) : "l"(a), "l"(b)); return r;
}
__device__ __forceinline__ u64 f2_mul(u64 a, u64 b) {
    u64 r; asm("mul.rn.f32x2 %0, %1, %2;" : "=l"(r) : "l"(a), "l"(b)); return r;
}
__device__ __forceinline__ u64 f2_fma(u64 a, u64 b, u64 c) {
    u64 r; asm("fma.rn.f32x2 %0, %1, %2, %3;" : "=l"(r) : "l"(a), "l"(b), "l"(c)); return r;
}
__device__ __forceinline__ void f2_unpack(u64 v, float& lo, float& hi) {
    asm("mov.b64 {%0, %1}, %2;" : "=f"(lo), "=f"(hi) : "l"(v));
}
__device__ __forceinline__ u64 f2_pack(float lo, float hi) {
    u64 r; asm("mov.b64 %0, {%1, %2};" : "=l"(r) : "f"(lo), "f"(hi)); return r;
}

#define F2_NEG1 0xBF800000BF800000ULL
#define F2_KK   0x3EB8AA3B3EB8AA3BULL   /* (KEXP, KEXP) as 2x f32 0x3EB8AA3B */

// ============================================================================
// k1: mean + dil. 512 blocks x 256 threads; block = (b, half-row of 1024 elems)
// ============================================================================
__global__ void __launch_bounds__(256) k_mean_dil(const float* __restrict__ ebp,
                                                  const float* __restrict__ ebg) {
    __shared__ float red[8][4];
    int b    = blockIdx.x >> 1;
    int d4   = ((blockIdx.x & 1) << 8) + threadIdx.x;   // 0..511
    int lane = threadIdx.x & 31, warp = threadIdx.x >> 5;

    if (blockIdx.x == 0 && threadIdx.x == 0) {          // state consumed only by k2
        g_acc1 = 0.0; g_ctr = 0u; g_done = 0u;
    }

    const float4* e4 = (const float4*)ebp;
    float sx = 0.f, sy = 0.f, sz = 0.f, sw = 0.f;
#pragma unroll 8
    for (int p = 0; p < PNUM; p++) {
        float4 v = e4[(p * BATCH + b) * D4 + d4];
        sx += v.x; sy += v.y; sz += v.z; sw += v.w;
    }
    const float inv = 1.0f / (float)PNUM;
    float4 m; m.x = sx * inv; m.y = sy * inv; m.z = sz * inv; m.w = sw * inv;
    ((float4*)g_mean)[b * D4 + d4] = m;

    float4 g = ((const float4*)(ebg + (size_t)b * DIM))[d4];
    float se_g = 0.f, se_m = 0.f, su_g = 0.f, su_m = 0.f;
#define DIL1(c) { float u = m.c - g.c;                      \
                  float eg = ex2f(g.c * KEXP);              \
                  float em = ex2f(m.c * KEXP);              \
                  se_g += eg; se_m += em;                   \
                  su_g = fmaf(eg, u, su_g);                 \
                  su_m = fmaf(em, u, su_m); }
    DIL1(x) DIL1(y) DIL1(z) DIL1(w)
#undef DIL1

#pragma unroll
    for (int off = 16; off; off >>= 1) {
        se_g += __shfl_xor_sync(0xffffffffu, se_g, off);
        se_m += __shfl_xor_sync(0xffffffffu, se_m, off);
        su_g += __shfl_xor_sync(0xffffffffu, su_g, off);
        su_m += __shfl_xor_sync(0xffffffffu, su_m, off);
    }
    if (lane == 0) { red[warp][0] = se_g; red[warp][1] = se_m;
                     red[warp][2] = su_g; red[warp][3] = su_m; }
    __syncthreads();
    if (warp == 0 && lane < 8) {
        float a = red[lane][0], c = red[lane][1], d = red[lane][2], e = red[lane][3];
#pragma unroll
        for (int off = 4; off; off >>= 1) {
            a += __shfl_xor_sync(0x000000ffu, a, off);
            c += __shfl_xor_sync(0x000000ffu, c, off);
            d += __shfl_xor_sync(0x000000ffu, d, off);
            e += __shfl_xor_sync(0x000000ffu, e, off);
        }
        if (lane == 0) { g_dil4[blockIdx.x][0] = a; g_dil4[blockIdx.x][1] = c;
                         g_dil4[blockIdx.x][2] = d; g_dil4[blockIdx.x][3] = e; }
    }
}

// ============================================================================
// k2: dcl (packed f32x2, warp-per-row work stealing) + last-block finalize
// ============================================================================
__global__ void __launch_bounds__(256) k_dcl(const float* __restrict__ ebg,
                                             const float* __restrict__ ebp,
                                             float* __restrict__ out) {
    __shared__ int s_last;
    int lane = threadIdx.x & 31;
    float local = 0.f;

    unsigned item = 0;
    if (lane == 0) item = atomicAdd(&g_ctr, 1u);
    item = __shfl_sync(0xffffffffu, item, 0);

    while (item < NROWS) {
        int b = (int)(item & (BATCH - 1));
        const ulonglong2* p2 = (const ulonglong2*)(ebp    + (size_t)item * DIM) + lane;
        const ulonglong2* g2 = (const ulonglong2*)(ebg    + (size_t)b    * DIM) + lane;
        const ulonglong2* m2 = (const ulonglong2*)(g_mean + (size_t)b    * DIM) + lane;

        u64 seX = 0, seY = 0, suX = 0, suY = 0;   // 0x0 == packed (0.f, 0.f)
#pragma unroll 4
        for (int i = 0; i < 16; i++) {
            ulonglong2 P = p2[i * 32];
            ulonglong2 G = g2[i * 32];
            ulonglong2 M = m2[i * 32];
#define DCL2(pp, gg, mm) {                                       \
            u64 dg = f2_fma(pp, F2_NEG1, gg);                    \
            u64 db = f2_fma(pp, F2_NEG1, mm);                    \
            u64 mg = f2_fma(gg, F2_NEG1, mm);                    \
            u64 w  = f2_add(db, dg);                             \
            u64 u  = f2_mul(mg, w);                              \
            u64 ax = f2_mul(f2_mul(dg, dg), F2_KK);              \
            u64 ay = f2_mul(f2_mul(db, db), F2_KK);              \
            float a0, a1, b0, b1;                                \
            f2_unpack(ax, a0, a1); f2_unpack(ay, b0, b1);        \
            u64 ex = f2_pack(ex2f(a0), ex2f(a1));                \
            u64 ey = f2_pack(ex2f(b0), ex2f(b1));                \
            seX = f2_add(seX, ex); seY = f2_add(seY, ey);        \
            suX = f2_fma(ex, u, suX); suY = f2_fma(ey, u, suY); }
            DCL2(P.x, G.x, M.x)
            DCL2(P.y, G.y, M.y)
#undef DCL2
        }
        float ex0, ex1, ey0, ey1, ux0, ux1, uy0, uy1;
        f2_unpack(seX, ex0, ex1); f2_unpack(seY, ey0, ey1);
        f2_unpack(suX, ux0, ux1); f2_unpack(suY, uy0, uy1);
        float se_x = ex0 + ex1, se_y = ey0 + ey1;
        float su_x = ux0 + ux1, su_y = uy0 + uy1;
#pragma unroll
        for (int off = 16; off; off >>= 1) {
            se_x += __shfl_xor_sync(0xffffffffu, se_x, off);
            se_y += __shfl_xor_sync(0xffffffffu, se_y, off);
            su_x += __shfl_xor_sync(0xffffffffu, su_x, off);
            su_y += __shfl_xor_sync(0xffffffffu, su_y, off);
        }
        local += su_y / se_y - su_x / se_x;

        if (lane == 0) item = atomicAdd(&g_ctr, 1u);
        item = __shfl_sync(0xffffffffu, item, 0);
    }

    if (lane == 0 && local != 0.f)
        atomicAdd(&g_acc1, (double)local * (4.0 / ((double)DIM * (double)PNUM)));

    // ---- last-block finalize (threadFenceReduction pattern) ----
    __threadfence();
    __syncthreads();
    if (threadIdx.x == 0) {
        unsigned prev = atomicAdd(&g_done, 1u);
        s_last = (prev == gridDim.x - 1) ? 1 : 0;
    }
    __syncthreads();
    if (s_last && threadIdx.x < 32) {
        __threadfence();
        double dil = 0.0;
#pragma unroll
        for (int bb = lane; bb < BATCH; bb += 32) {
            float seg = g_dil4[2 * bb][0] + g_dil4[2 * bb + 1][0];
            float sem = g_dil4[2 * bb][1] + g_dil4[2 * bb + 1][1];
            float sug = g_dil4[2 * bb][2] + g_dil4[2 * bb + 1][2];
            float sum = g_dil4[2 * bb][3] + g_dil4[2 * bb + 1][3];
            dil += (double)(sum / sem - sug / seg);
        }
#pragma unroll
        for (int off = 16; off; off >>= 1)
            dil += __shfl_xor_sync(0xffffffffu, dil, off);
        if (lane == 0) {
            out[0] = (float)(dil * (4.0 / (double)DIM));
            out[1] = (float)(*(volatile double*)&g_acc1);
        }
    }
}

extern "C" void kernel_launch(void* const* d_in, const int* in_sizes, int n_in,
                              void* d_out, int out_size) {
    const float* ebg = (const float*)d_in[0];
    const float* ebp = (const float*)d_in[1];
    (void)in_sizes; (void)n_in; (void)out_size;

    k_mean_dil<<<512, 256>>>(ebp, ebg);
    k_dcl<<<GRID2, 256>>>(ebg, ebp, (float*)d_out);
}

// round 4
// speedup vs baseline: 1.4294x; 1.3293x over previous
#include <cuda_runtime.h>
#include <cstdint>

#define BATCH 256
#define DIM   2048
#define PNUM  56
#define NROWS (PNUM * BATCH)          // 14336
#define D4    (DIM / 4)               // 512 float4 per row
#define TILES 7
#define NP    8                       // p-rows per block
#define GRID2 (BATCH * TILES)         // 1792

// log2(e)/T with T=4
#define KEXP  0.3606737602222409f

typedef unsigned long long u64;

// --- device scratch ---
__device__ double       g_acc1;               // dcl accumulator
__device__ unsigned int g_done;               // finished-block counter for dcl
__device__ float        g_mean[BATCH * DIM];  // ebp_bar
__device__ float        g_dil4[512][4];       // per (b,half): se_g, se_m, su_g, su_m

__device__ __forceinline__ float ex2f(float x) {
    float r; asm("ex2.approx.ftz.f32 %0, %1;" : "=f"(r) : "f"(x)); return r;
}
__device__ __forceinline__ u64 f2_add(u64 a, u64 b) {
    u64 r; asm("add.rn.f32x2 %0, %1, %2;" : "=l"(r) : "l"(a), "l"(b)); return r;
}
__device__ __forceinline__ u64 f2_mul(u64 a, u64 b) {
    u64 r; asm("mul.rn.f32x2 %0, %1, %2;" : "=l"(r) : "l"(a), "l"(b)); return r;
}
__device__ __forceinline__ u64 f2_fma(u64 a, u64 b, u64 c) {
    u64 r; asm("fma.rn.f32x2 %0, %1, %2, %3;" : "=l"(r) : "l"(a), "l"(b), "l"(c)); return r;
}
__device__ __forceinline__ void f2_unpack(u64 v, float& lo, float& hi) {
    asm("mov.b64 {%0, %1}, %2;" : "=f"(lo), "=f"(hi) : "l"(v));
}
__device__ __forceinline__ u64 f2_pack(float lo, float hi) {
    u64 r; asm("mov.b64 %0, {%1, %2};" : "=l"(r) : "f"(lo), "f"(hi)); return r;
}

#define F2_NEG1 0xBF800000BF800000ULL
#define F2_KK   0x3EB8AA3B3EB8AA3BULL   /* (KEXP, KEXP) packed f32x2 */

// ============================================================================
// k1: mean + dil. 512 blocks x 256 threads; block = (b, half-row of 1024 elems)
// ============================================================================
__global__ void __launch_bounds__(256) k_mean_dil(const float* __restrict__ ebp,
                                                  const float* __restrict__ ebg) {
    __shared__ float red[8][4];
    int b    = blockIdx.x >> 1;
    int d4   = ((blockIdx.x & 1) << 8) + threadIdx.x;   // 0..511
    int lane = threadIdx.x & 31, warp = threadIdx.x >> 5;

    if (blockIdx.x == 0 && threadIdx.x == 0) {          // state consumed only by k2
        g_acc1 = 0.0; g_done = 0u;
    }

    const float4* e4 = (const float4*)ebp;
    float sx = 0.f, sy = 0.f, sz = 0.f, sw = 0.f;
#pragma unroll 8
    for (int p = 0; p < PNUM; p++) {
        float4 v = e4[(p * BATCH + b) * D4 + d4];
        sx += v.x; sy += v.y; sz += v.z; sw += v.w;
    }
    const float inv = 1.0f / (float)PNUM;
    float4 m; m.x = sx * inv; m.y = sy * inv; m.z = sz * inv; m.w = sw * inv;
    ((float4*)g_mean)[b * D4 + d4] = m;

    float4 g = ((const float4*)(ebg + (size_t)b * DIM))[d4];
    float se_g = 0.f, se_m = 0.f, su_g = 0.f, su_m = 0.f;
#define DIL1(c) { float u = m.c - g.c;                      \
                  float eg = ex2f(g.c * KEXP);              \
                  float em = ex2f(m.c * KEXP);              \
                  se_g += eg; se_m += em;                   \
                  su_g = fmaf(eg, u, su_g);                 \
                  su_m = fmaf(em, u, su_m); }
    DIL1(x) DIL1(y) DIL1(z) DIL1(w)
#undef DIL1

#pragma unroll
    for (int off = 16; off; off >>= 1) {
        se_g += __shfl_xor_sync(0xffffffffu, se_g, off);
        se_m += __shfl_xor_sync(0xffffffffu, se_m, off);
        su_g += __shfl_xor_sync(0xffffffffu, su_g, off);
        su_m += __shfl_xor_sync(0xffffffffu, su_m, off);
    }
    if (lane == 0) { red[warp][0] = se_g; red[warp][1] = se_m;
                     red[warp][2] = su_g; red[warp][3] = su_m; }
    __syncthreads();
    if (warp == 0 && lane < 8) {
        float a = red[lane][0], c = red[lane][1], d = red[lane][2], e = red[lane][3];
#pragma unroll
        for (int off = 4; off; off >>= 1) {
            a += __shfl_xor_sync(0x000000ffu, a, off);
            c += __shfl_xor_sync(0x000000ffu, c, off);
            d += __shfl_xor_sync(0x000000ffu, d, off);
            e += __shfl_xor_sync(0x000000ffu, e, off);
        }
        if (lane == 0) { g_dil4[blockIdx.x][0] = a; g_dil4[blockIdx.x][1] = c;
                         g_dil4[blockIdx.x][2] = d; g_dil4[blockIdx.x][3] = e; }
    }
}

// ============================================================================
// k2: dcl. Block = (b, tile of NP=8 p-rows), 128 threads. g/m cached in smem;
// only the ebp stream hits DRAM. Packed f32x2 math. Last block finalizes out.
// ============================================================================
__global__ void __launch_bounds__(128) k_dcl(const float* __restrict__ ebg,
                                             const float* __restrict__ ebp,
                                             float* __restrict__ out) {
    __shared__ float4 s_g[D4];
    __shared__ float4 s_m[D4];
    __shared__ int s_last;

    int b    = blockIdx.x / TILES;
    int tile = blockIdx.x - b * TILES;
    int tid  = threadIdx.x;
    int lane = tid & 31, warp = tid >> 5;

    // cooperative fill: 512 float4 per row, 128 threads -> 4 each
    const float4* g4 = (const float4*)(ebg    + (size_t)b * DIM);
    const float4* m4 = (const float4*)(g_mean + (size_t)b * DIM);
#pragma unroll
    for (int i = 0; i < 4; i++) {
        s_g[tid + 128 * i] = g4[tid + 128 * i];
        s_m[tid + 128 * i] = m4[tid + 128 * i];
    }
    __syncthreads();

    const ulonglong2* g2 = (const ulonglong2*)s_g + lane;
    const ulonglong2* m2 = (const ulonglong2*)s_m + lane;

    float local = 0.f;
#pragma unroll
    for (int rr = 0; rr < 2; rr++) {
        int p   = tile * NP + warp * 2 + rr;            // 0..55
        int row = p * BATCH + b;
        const ulonglong2* p2 = (const ulonglong2*)(ebp + (size_t)row * DIM) + lane;

        u64 seX = 0, seY = 0, suX = 0, suY = 0;         // packed (0,0)
#pragma unroll 4
        for (int i = 0; i < 16; i++) {
            ulonglong2 P = p2[i * 32];
            ulonglong2 G = g2[i * 32];
            ulonglong2 M = m2[i * 32];
#define DCL2(pp, gg, mm) {                                       \
            u64 dg = f2_fma(pp, F2_NEG1, gg);                    \
            u64 db = f2_fma(pp, F2_NEG1, mm);                    \
            u64 mg = f2_fma(gg, F2_NEG1, mm);                    \
            u64 w  = f2_add(db, dg);                             \
            u64 u  = f2_mul(mg, w);                              \
            u64 ax = f2_mul(f2_mul(dg, dg), F2_KK);              \
            u64 ay = f2_mul(f2_mul(db, db), F2_KK);              \
            float a0, a1, b0, b1;                                \
            f2_unpack(ax, a0, a1); f2_unpack(ay, b0, b1);        \
            u64 ex = f2_pack(ex2f(a0), ex2f(a1));                \
            u64 ey = f2_pack(ex2f(b0), ex2f(b1));                \
            seX = f2_add(seX, ex); seY = f2_add(seY, ey);        \
            suX = f2_fma(ex, u, suX); suY = f2_fma(ey, u, suY); }
            DCL2(P.x, G.x, M.x)
            DCL2(P.y, G.y, M.y)
#undef DCL2
        }
        float ex0, ex1, ey0, ey1, ux0, ux1, uy0, uy1;
        f2_unpack(seX, ex0, ex1); f2_unpack(seY, ey0, ey1);
        f2_unpack(suX, ux0, ux1); f2_unpack(suY, uy0, uy1);
        float se_x = ex0 + ex1, se_y = ey0 + ey1;
        float su_x = ux0 + ux1, su_y = uy0 + uy1;
#pragma unroll
        for (int off = 16; off; off >>= 1) {
            se_x += __shfl_xor_sync(0xffffffffu, se_x, off);
            se_y += __shfl_xor_sync(0xffffffffu, se_y, off);
            su_x += __shfl_xor_sync(0xffffffffu, su_x, off);
            su_y += __shfl_xor_sync(0xffffffffu, su_y, off);
        }
        local += su_y / se_y - su_x / se_x;
    }

    if (lane == 0)
        atomicAdd(&g_acc1, (double)local * (4.0 / ((double)DIM * (double)PNUM)));

    // ---- last-block finalize ----
    __threadfence();
    __syncthreads();
    if (tid == 0) {
        unsigned prev = atomicAdd(&g_done, 1u);
        s_last = (prev == gridDim.x - 1) ? 1 : 0;
    }
    __syncthreads();
    if (s_last && tid < 32) {
        __threadfence();
        double dil = 0.0;
#pragma unroll
        for (int bb = lane; bb < BATCH; bb += 32) {
            float seg = g_dil4[2 * bb][0] + g_dil4[2 * bb + 1][0];
            float sem = g_dil4[2 * bb][1] + g_dil4[2 * bb + 1][1];
            float sug = g_dil4[2 * bb][2] + g_dil4[2 * bb + 1][2];
            float sum = g_dil4[2 * bb][3] + g_dil4[2 * bb + 1][3];
            dil += (double)(sum / sem - sug / seg);
        }
#pragma unroll
        for (int off = 16; off; off >>= 1)
            dil += __shfl_xor_sync(0xffffffffu, dil, off);
        if (lane == 0) {
            out[0] = (float)(dil * (4.0 / (double)DIM));
            out[1] = (float)(*(volatile double*)&g_acc1);
        }
    }
}

extern "C" void kernel_launch(void* const* d_in, const int* in_sizes, int n_in,
                              void* d_out, int out_size) {
    const float* ebg = (const float*)d_in[0];
    const float* ebp = (const float*)d_in[1];
    (void)in_sizes; (void)n_in; (void)out_size;

    k_mean_dil<<<512, 256>>>(ebp, ebg);
    k_dcl<<<GRID2, 128>>>(ebg, ebp, (float*)d_out);
}

// round 5
// speedup vs baseline: 1.4761x; 1.0326x over previous
#include <cuda_runtime.h>
#include <cstdint>

#define BATCH 256
#define DIM   2048
#define PNUM  56
#define D4    (DIM / 4)               // 512 float4 per row
#define TILES 7
#define NP    8                       // p-rows per block (4 warps x 2 rows)
#define GRID2 (BATCH * TILES)         // 1792

// log2(e)/T with T=4
#define KEXP  0.3606737602222409f

typedef unsigned long long u64;

// --- device scratch ---
__device__ double       g_acc1;               // dcl accumulator
__device__ unsigned int g_done;               // finished-block counter for dcl
__device__ float        g_mean[BATCH * DIM];  // ebp_bar
__device__ float        g_dil4[512][4];       // per (b,half): se_g, se_m, su_g, su_m

__device__ __forceinline__ float ex2f(float x) {
    float r; asm("ex2.approx.ftz.f32 %0, %1;" : "=f"(r) : "f"(x)); return r;
}
__device__ __forceinline__ u64 f2_add(u64 a, u64 b) {
    u64 r; asm("add.rn.f32x2 %0, %1, %2;" : "=l"(r) : "l"(a), "l"(b)); return r;
}
__device__ __forceinline__ u64 f2_mul(u64 a, u64 b) {
    u64 r; asm("mul.rn.f32x2 %0, %1, %2;" : "=l"(r) : "l"(a), "l"(b)); return r;
}
__device__ __forceinline__ u64 f2_fma(u64 a, u64 b, u64 c) {
    u64 r; asm("fma.rn.f32x2 %0, %1, %2, %3;" : "=l"(r) : "l"(a), "l"(b), "l"(c)); return r;
}
__device__ __forceinline__ void f2_unpack(u64 v, float& lo, float& hi) {
    asm("mov.b64 {%0, %1}, %2;" : "=f"(lo), "=f"(hi) : "l"(v));
}
__device__ __forceinline__ u64 f2_pack(float lo, float hi) {
    u64 r; asm("mov.b64 %0, {%1, %2};" : "=l"(r) : "f"(lo), "f"(hi)); return r;
}

#define F2_NEG1 0xBF800000BF800000ULL
#define F2_KK   0x3EB8AA3B3EB8AA3BULL   /* (KEXP, KEXP) packed f32x2 */

// ============================================================================
// k1: mean + dil. 512 blocks x 256 threads; block = (b, half-row of 1024 elems)
// ============================================================================
__global__ void __launch_bounds__(256) k_mean_dil(const float* __restrict__ ebp,
                                                  const float* __restrict__ ebg) {
    __shared__ float red[8][4];
    int b    = blockIdx.x >> 1;
    int d4   = ((blockIdx.x & 1) << 8) + threadIdx.x;   // 0..511
    int lane = threadIdx.x & 31, warp = threadIdx.x >> 5;

    if (blockIdx.x == 0 && threadIdx.x == 0) {          // state consumed only by k2
        g_acc1 = 0.0; g_done = 0u;
    }

    const float4* e4 = (const float4*)ebp;
    float sx = 0.f, sy = 0.f, sz = 0.f, sw = 0.f;
#pragma unroll 8
    for (int p = 0; p < PNUM; p++) {
        float4 v = e4[(p * BATCH + b) * D4 + d4];
        sx += v.x; sy += v.y; sz += v.z; sw += v.w;
    }
    const float inv = 1.0f / (float)PNUM;
    float4 m; m.x = sx * inv; m.y = sy * inv; m.z = sz * inv; m.w = sw * inv;
    ((float4*)g_mean)[b * D4 + d4] = m;

    float4 g = ((const float4*)(ebg + (size_t)b * DIM))[d4];
    float se_g = 0.f, se_m = 0.f, su_g = 0.f, su_m = 0.f;
#define DIL1(c) { float u = m.c - g.c;                      \
                  float eg = ex2f(g.c * KEXP);              \
                  float em = ex2f(m.c * KEXP);              \
                  se_g += eg; se_m += em;                   \
                  su_g = fmaf(eg, u, su_g);                 \
                  su_m = fmaf(em, u, su_m); }
    DIL1(x) DIL1(y) DIL1(z) DIL1(w)
#undef DIL1

#pragma unroll
    for (int off = 16; off; off >>= 1) {
        se_g += __shfl_xor_sync(0xffffffffu, se_g, off);
        se_m += __shfl_xor_sync(0xffffffffu, se_m, off);
        su_g += __shfl_xor_sync(0xffffffffu, su_g, off);
        su_m += __shfl_xor_sync(0xffffffffu, su_m, off);
    }
    if (lane == 0) { red[warp][0] = se_g; red[warp][1] = se_m;
                     red[warp][2] = su_g; red[warp][3] = su_m; }
    __syncthreads();
    if (warp == 0 && lane < 8) {
        float a = red[lane][0], c = red[lane][1], d = red[lane][2], e = red[lane][3];
#pragma unroll
        for (int off = 4; off; off >>= 1) {
            a += __shfl_xor_sync(0x000000ffu, a, off);
            c += __shfl_xor_sync(0x000000ffu, c, off);
            d += __shfl_xor_sync(0x000000ffu, d, off);
            e += __shfl_xor_sync(0x000000ffu, e, off);
        }
        if (lane == 0) { g_dil4[blockIdx.x][0] = a; g_dil4[blockIdx.x][1] = c;
                         g_dil4[blockIdx.x][2] = d; g_dil4[blockIdx.x][3] = e; }
    }
}

// ============================================================================
// k2: dcl. Block = (b, tile of 8 p-rows), 128 threads, warp handles TWO rows
// interleaved (2 independent LDG streams + shared g/m from smem) to double
// per-warp ILP/MLP. Packed f32x2 math. Last block finalizes the output.
// ============================================================================
__global__ void __launch_bounds__(128) k_dcl(const float* __restrict__ ebg,
                                             const float* __restrict__ ebp,
                                             float* __restrict__ out) {
    __shared__ float4 s_g[D4];
    __shared__ float4 s_m[D4];
    __shared__ int s_last;

    int b    = blockIdx.x / TILES;
    int tile = blockIdx.x - b * TILES;
    int tid  = threadIdx.x;
    int lane = tid & 31, warp = tid >> 5;

    const float4* g4 = (const float4*)(ebg    + (size_t)b * DIM);
    const float4* m4 = (const float4*)(g_mean + (size_t)b * DIM);
#pragma unroll
    for (int i = 0; i < 4; i++) {
        s_g[tid + 128 * i] = g4[tid + 128 * i];
        s_m[tid + 128 * i] = m4[tid + 128 * i];
    }
    __syncthreads();

    const ulonglong2* g2 = (const ulonglong2*)s_g + lane;
    const ulonglong2* m2 = (const ulonglong2*)s_m + lane;

    int pA = tile * NP + warp * 2;
    const ulonglong2* p2A = (const ulonglong2*)(ebp + (size_t)(pA * BATCH + b) * DIM) + lane;
    const ulonglong2* p2B = (const ulonglong2*)(ebp + (size_t)((pA + 1) * BATCH + b) * DIM) + lane;

    u64 seXA = 0, seYA = 0, suXA = 0, suYA = 0;
    u64 seXB = 0, seYB = 0, suXB = 0, suYB = 0;

#pragma unroll 4
    for (int i = 0; i < 16; i++) {
        ulonglong2 P = p2A[i * 32];
        ulonglong2 Q = p2B[i * 32];
        ulonglong2 G = g2[i * 32];
        ulonglong2 M = m2[i * 32];
        // shared mg = m - g for both rows
        u64 mgx = f2_fma(G.x, F2_NEG1, M.x);
        u64 mgy = f2_fma(G.y, F2_NEG1, M.y);
#define DCL2(pp, gg, mm, mg, seX, seY, suX, suY) {               \
            u64 dg = f2_fma(pp, F2_NEG1, gg);                    \
            u64 db = f2_fma(pp, F2_NEG1, mm);                    \
            u64 w  = f2_add(db, dg);                             \
            u64 u  = f2_mul(mg, w);                              \
            u64 ax = f2_mul(f2_mul(dg, dg), F2_KK);              \
            u64 ay = f2_mul(f2_mul(db, db), F2_KK);              \
            float a0, a1, b0, b1;                                \
            f2_unpack(ax, a0, a1); f2_unpack(ay, b0, b1);        \
            u64 ex = f2_pack(ex2f(a0), ex2f(a1));                \
            u64 ey = f2_pack(ex2f(b0), ex2f(b1));                \
            seX = f2_add(seX, ex); seY = f2_add(seY, ey);        \
            suX = f2_fma(ex, u, suX); suY = f2_fma(ey, u, suY); }
        DCL2(P.x, G.x, M.x, mgx, seXA, seYA, suXA, suYA)
        DCL2(Q.x, G.x, M.x, mgx, seXB, seYB, suXB, suYB)
        DCL2(P.y, G.y, M.y, mgy, seXA, seYA, suXA, suYA)
        DCL2(Q.y, G.y, M.y, mgy, seXB, seYB, suXB, suYB)
#undef DCL2
    }

    float local;
    {
        float x0, x1, y0, y1, u0, u1, v0, v1;
        f2_unpack(seXA, x0, x1); f2_unpack(seYA, y0, y1);
        f2_unpack(suXA, u0, u1); f2_unpack(suYA, v0, v1);
        float seA_x = x0 + x1, seA_y = y0 + y1, suA_x = u0 + u1, suA_y = v0 + v1;
        f2_unpack(seXB, x0, x1); f2_unpack(seYB, y0, y1);
        f2_unpack(suXB, u0, u1); f2_unpack(suYB, v0, v1);
        float seB_x = x0 + x1, seB_y = y0 + y1, suB_x = u0 + u1, suB_y = v0 + v1;
#pragma unroll
        for (int off = 16; off; off >>= 1) {
            seA_x += __shfl_xor_sync(0xffffffffu, seA_x, off);
            seA_y += __shfl_xor_sync(0xffffffffu, seA_y, off);
            suA_x += __shfl_xor_sync(0xffffffffu, suA_x, off);
            suA_y += __shfl_xor_sync(0xffffffffu, suA_y, off);
            seB_x += __shfl_xor_sync(0xffffffffu, seB_x, off);
            seB_y += __shfl_xor_sync(0xffffffffu, seB_y, off);
            suB_x += __shfl_xor_sync(0xffffffffu, suB_x, off);
            suB_y += __shfl_xor_sync(0xffffffffu, suB_y, off);
        }
        local = (suA_y / seA_y - suA_x / seA_x) + (suB_y / seB_y - suB_x / seB_x);
    }

    if (lane == 0)
        atomicAdd(&g_acc1, (double)local * (4.0 / ((double)DIM * (double)PNUM)));

    // ---- last-block finalize ----
    __threadfence();
    __syncthreads();
    if (tid == 0) {
        unsigned prev = atomicAdd(&g_done, 1u);
        s_last = (prev == gridDim.x - 1) ? 1 : 0;
    }
    __syncthreads();
    if (s_last && tid < 32) {
        __threadfence();
        double dil = 0.0;
#pragma unroll
        for (int bb = lane; bb < BATCH; bb += 32) {
            float seg = g_dil4[2 * bb][0] + g_dil4[2 * bb + 1][0];
            float sem = g_dil4[2 * bb][1] + g_dil4[2 * bb + 1][1];
            float sug = g_dil4[2 * bb][2] + g_dil4[2 * bb + 1][2];
            float sum = g_dil4[2 * bb][3] + g_dil4[2 * bb + 1][3];
            dil += (double)(sum / sem - sug / seg);
        }
#pragma unroll
        for (int off = 16; off; off >>= 1)
            dil += __shfl_xor_sync(0xffffffffu, dil, off);
        if (lane == 0) {
            out[0] = (float)(dil * (4.0 / (double)DIM));
            out[1] = (float)(*(volatile double*)&g_acc1);
        }
    }
}

extern "C" void kernel_launch(void* const* d_in, const int* in_sizes, int n_in,
                              void* d_out, int out_size) {
    const float* ebg = (const float*)d_in[0];
    const float* ebp = (const float*)d_in[1];
    (void)in_sizes; (void)n_in; (void)out_size;

    k_mean_dil<<<512, 256>>>(ebp, ebg);
    k_dcl<<<GRID2, 128>>>(ebg, ebp, (float*)d_out);
}

// round 7
// speedup vs baseline: 1.5651x; 1.0603x over previous
#include <cuda_runtime.h>
#include <cstdint>

#define BATCH 256
#define DIM   2048
#define PNUM  56
#define CH    8                        // column chunks per batch row
#define C4    64                       // float4 per chunk (256 floats)
#define RPAD  260                      // padded row length in floats (65 x 16B)
#define GRID1 (BATCH * CH)             // 2048
#define NDCL  (BATCH * PNUM / 8)       // 1792 dcl blocks in k2
#define GRID2 (NDCL + 1)               // + 1 dil block

// smem layout (floats)
#define S_P    0                       // 56 x 260
#define S_M    (56 * RPAD)             // 14560: mean, 256 floats
#define S_MG   (S_M + 256)             // 14816: m - g, 256 floats
#define S_RED  (S_MG + 256)            // 15072: 4 x 256 mean partials
#define SMEMF  (S_RED + 1024)          // 16096 floats = 64384 bytes

#define KEXP  0.3606737602222409f

typedef unsigned long long u64;

__device__ double       g_acc1;
__device__ unsigned int g_done;
__device__ float4       scr_dcl[GRID1 * 224];   // per (b,ch): 56 rows x 4 subchunks
__device__ float4       scr_dil[GRID1 * 2];     // per (b,ch): 2 warp partials

__device__ __forceinline__ float ex2f(float x) {
    float r; asm("ex2.approx.ftz.f32 %0, %1;" : "=f"(r) : "f"(x)); return r;
}
__device__ __forceinline__ u64 f2_add(u64 a, u64 b) {
    u64 r; asm("add.rn.f32x2 %0, %1, %2;" : "=l"(r) : "l"(a), "l"(b)); return r;
}
__device__ __forceinline__ u64 f2_mul(u64 a, u64 b) {
    u64 r; asm("mul.rn.f32x2 %0, %1, %2;" : "=l"(r) : "l"(a), "l"(b)); return r;
}
__device__ __forceinline__ u64 f2_fma(u64 a, u64 b, u64 c) {
    u64 r; asm("fma.rn.f32x2 %0, %1, %2, %3;" : "=l"(r) : "l"(a), "l"(b), "l"(c)); return r;
}
__device__ __forceinline__ void f2_unpack(u64 v, float& lo, float& hi) {
    asm("mov.b64 {%0, %1}, %2;" : "=f"(lo), "=f"(hi) : "l"(v));
}
__device__ __forceinline__ u64 f2_pack(float lo, float hi) {
    u64 r; asm("mov.b64 %0, {%1, %2};" : "=l"(r) : "f"(lo), "f"(hi)); return r;
}

#define F2_NEG1 0xBF800000BF800000ULL
#define F2_KK   0x3EB8AA3B3EB8AA3BULL   /* (KEXP, KEXP) */
#define F2_I56  0x3C9249253C924925ULL   /* (1/56, 1/56) */

// ============================================================================
// k1: single pass over ebp. Block = (b, chunk). Phase A: load 56 rows into
// smem + accumulate mean in-flight. Mid: finalize m, mg, dil partials.
// Phase C: thread = (row, 64-col subchunk) computes dcl partials, no shuffles.
// ============================================================================
__global__ void __launch_bounds__(256, 3) k1(const float* __restrict__ ebp,
                                             const float* __restrict__ ebg) {
    extern __shared__ float sm[];
    int b  = blockIdx.x >> 3;
    int ch = blockIdx.x & 7;
    int tid = threadIdx.x;

    if (blockIdx.x == 0 && tid == 0) { g_acc1 = 0.0; g_done = 0u; }

    // ---- Phase A: load + mean ----
    int rg = tid >> 6;          // row group 0..3
    int c4 = tid & 63;          // float4 index within chunk
    const ulonglong2* eb = (const ulonglong2*)ebp;
    size_t coff = (size_t)ch * C4 + c4;
    u64 aLo = 0, aHi = 0;       // packed mean accum for this thread's 4 cols
#pragma unroll 14
    for (int i = 0; i < 14; i++) {
        int p = i * 4 + rg;
        ulonglong2 v = eb[(size_t)(p * BATCH + b) * 512 + coff];
        *(ulonglong2*)&sm[S_P + p * RPAD + c4 * 4] = v;
        aLo = f2_add(aLo, v.x);
        aHi = f2_add(aHi, v.y);
    }
    *(ulonglong2*)&sm[S_RED + rg * 256 + c4 * 4] = make_ulonglong2(aLo, aHi);
    __syncthreads();

    // ---- Mid: finalize mean, mg, dil partials (threads 0..63) ----
    if (tid < 64) {
        ulonglong2 r0 = *(ulonglong2*)&sm[S_RED + 0 * 256 + tid * 4];
        ulonglong2 r1 = *(ulonglong2*)&sm[S_RED + 1 * 256 + tid * 4];
        ulonglong2 r2 = *(ulonglong2*)&sm[S_RED + 2 * 256 + tid * 4];
        ulonglong2 r3 = *(ulonglong2*)&sm[S_RED + 3 * 256 + tid * 4];
        u64 mLo = f2_mul(f2_add(f2_add(r0.x, r1.x), f2_add(r2.x, r3.x)), F2_I56);
        u64 mHi = f2_mul(f2_add(f2_add(r0.y, r1.y), f2_add(r2.y, r3.y)), F2_I56);
        ulonglong2 g = ((const ulonglong2*)ebg)[(size_t)b * 512 + coff];
        u64 mgLo = f2_fma(g.x, F2_NEG1, mLo);
        u64 mgHi = f2_fma(g.y, F2_NEG1, mHi);
        *(ulonglong2*)&sm[S_M  + tid * 4] = make_ulonglong2(mLo, mHi);
        *(ulonglong2*)&sm[S_MG + tid * 4] = make_ulonglong2(mgLo, mgHi);

        // dil partials for these 4 cols
        float m0, m1, m2, m3, g0, g1, g2, g3, u0, u1, u2, u3;
        f2_unpack(mLo, m0, m1); f2_unpack(mHi, m2, m3);
        f2_unpack(g.x, g0, g1); f2_unpack(g.y, g2, g3);
        f2_unpack(mgLo, u0, u1); f2_unpack(mgHi, u2, u3);
        float se_g = 0.f, se_m = 0.f, su_g = 0.f, su_m = 0.f;
#define DIL1(gg, mm, uu) { float eg = ex2f(gg * KEXP);          \
                           float em = ex2f(mm * KEXP);          \
                           se_g += eg; se_m += em;              \
                           su_g = fmaf(eg, uu, su_g);           \
                           su_m = fmaf(em, uu, su_m); }
        DIL1(g0, m0, u0) DIL1(g1, m1, u1) DIL1(g2, m2, u2) DIL1(g3, m3, u3)
#undef DIL1
#pragma unroll
        for (int off = 16; off; off >>= 1) {
            se_g += __shfl_xor_sync(0xffffffffu, se_g, off);
            se_m += __shfl_xor_sync(0xffffffffu, se_m, off);
            su_g += __shfl_xor_sync(0xffffffffu, su_g, off);
            su_m += __shfl_xor_sync(0xffffffffu, su_m, off);
        }
        if ((tid & 31) == 0)
            scr_dil[blockIdx.x * 2 + (tid >> 5)] =
                make_float4(se_g, se_m, su_g, su_m);
    }
    __syncthreads();

    // ---- Phase C: per-thread dcl partials ----
    int s = tid / 56;                  // subchunk 0..3 (tid>=224 idle)
    int r = tid - s * 56;              // row 0..55
    if (s < 4) {
        int j0 = s * 16;               // float4 base within chunk
        u64 seX = 0, seY = 0, suX = 0, suY = 0;
#pragma unroll 16
        for (int j = 0; j < 16; j++) {
            ulonglong2 P  = *(ulonglong2*)&sm[S_P  + r * RPAD + (j0 + j) * 4];
            ulonglong2 M  = *(ulonglong2*)&sm[S_M  + (j0 + j) * 4];
            ulonglong2 MG = *(ulonglong2*)&sm[S_MG + (j0 + j) * 4];
#define DCLP(pp, mm, gm) {                                       \
            u64 db = f2_fma(pp, F2_NEG1, mm);    /* m - p */     \
            u64 dg = f2_fma(gm, F2_NEG1, db);    /* g - p */     \
            u64 w  = f2_add(db, dg);                             \
            u64 u  = f2_mul(gm, w);                              \
            u64 ax = f2_mul(f2_mul(dg, dg), F2_KK);              \
            u64 ay = f2_mul(f2_mul(db, db), F2_KK);              \
            float a0, a1, b0, b1;                                \
            f2_unpack(ax, a0, a1); f2_unpack(ay, b0, b1);        \
            u64 ex = f2_pack(ex2f(a0), ex2f(a1));                \
            u64 ey = f2_pack(ex2f(b0), ex2f(b1));                \
            seX = f2_add(seX, ex); seY = f2_add(seY, ey);        \
            suX = f2_fma(ex, u, suX); suY = f2_fma(ey, u, suY); }
            DCLP(P.x, M.x, MG.x)
            DCLP(P.y, M.y, MG.y)
#undef DCLP
        }
        float x0, x1, y0, y1, z0, z1, w0, w1;
        f2_unpack(seX, x0, x1); f2_unpack(seY, y0, y1);
        f2_unpack(suX, z0, z1); f2_unpack(suY, w0, w1);
        scr_dcl[blockIdx.x * 224 + r * 4 + s] =
            make_float4(x0 + x1, y0 + y1, z0 + z1, w0 + w1);
    }
}

// ============================================================================
// k2: combine partials. Blocks 0..NDCL-1: 8 warps x 1 (b,p) row each -> dcl.
// Block NDCL: dil. Last finished block writes out[1].
// ============================================================================
__global__ void __launch_bounds__(256) k2(float* __restrict__ out) {
    __shared__ double sacc[8];
    __shared__ int s_last;
    int tid = threadIdx.x, lane = tid & 31, w = tid >> 5;

    if (blockIdx.x < NDCL) {
        int row = blockIdx.x * 8 + w;          // 0..14335
        int b = row / PNUM, p = row - b * PNUM;
        float4 v = scr_dcl[(b * 8 + (lane >> 2)) * 224 + p * 4 + (lane & 3)];
#pragma unroll
        for (int off = 16; off; off >>= 1) {
            v.x += __shfl_xor_sync(0xffffffffu, v.x, off);
            v.y += __shfl_xor_sync(0xffffffffu, v.y, off);
            v.z += __shfl_xor_sync(0xffffffffu, v.z, off);
            v.w += __shfl_xor_sync(0xffffffffu, v.w, off);
        }
        if (lane == 0) sacc[w] = (double)(v.w / v.y - v.z / v.x);
        __syncthreads();
        if (tid == 0) {
            double s = 0.0;
#pragma unroll
            for (int i = 0; i < 8; i++) s += sacc[i];
            atomicAdd(&g_acc1, s);
        }
    } else {
        // dil: thread tid handles batch b = tid (scr_dil idx (b*8+ch)*2+w = b*16..b*16+15)
        float se_g = 0.f, se_m = 0.f, su_g = 0.f, su_m = 0.f;
#pragma unroll
        for (int i = 0; i < 16; i++) {
            float4 v = scr_dil[tid * 16 + i];
            se_g += v.x; se_m += v.y; su_g += v.z; su_m += v.w;
        }
        double d = (double)(su_m / se_m - su_g / se_g);
#pragma unroll
        for (int off = 16; off; off >>= 1)
            d += __shfl_xor_sync(0xffffffffu, d, off);
        if (lane == 0) sacc[w] = d;
        __syncthreads();
        if (tid == 0) {
            double s = 0.0;
#pragma unroll
            for (int i = 0; i < 8; i++) s += sacc[i];
            out[0] = (float)(s * (4.0 / (double)DIM));
        }
    }

    __threadfence();
    __syncthreads();
    if (tid == 0) {
        unsigned prev = atomicAdd(&g_done, 1u);
        s_last = (prev == gridDim.x - 1) ? 1 : 0;
    }
    __syncthreads();
    if (s_last && tid == 0) {
        __threadfence();
        double a = *(volatile double*)&g_acc1;
        out[1] = (float)(a * (4.0 / ((double)DIM * (double)PNUM)));
    }
}

extern "C" void kernel_launch(void* const* d_in, const int* in_sizes, int n_in,
                              void* d_out, int out_size) {
    const float* ebg = (const float*)d_in[0];
    const float* ebp = (const float*)d_in[1];
    (void)in_sizes; (void)n_in; (void)out_size;

    cudaFuncSetAttribute(k1, cudaFuncAttributeMaxDynamicSharedMemorySize,
                         SMEMF * sizeof(float));
    k1<<<GRID1, 256, SMEMF * sizeof(float)>>>(ebp, ebg);
    k2<<<GRID2, 256>>>((float*)d_out);
}

// round 8
// speedup vs baseline: 1.9266x; 1.2310x over previous
#include <cuda_runtime.h>
#include <cstdint>

#define BATCH 256
#define DIM   2048
#define PNUM  56
#define CH    8                        // column chunks per batch row
#define C4    64                       // float4 per chunk (256 floats)
#define RPAD  260                      // padded row length in floats (65 x 16B)
#define GRID1 (BATCH * CH)             // 2048

// smem layout (floats)
#define S_P    0                       // 56 x 260
#define S_M    (56 * RPAD)             // 14560: mean, 256 floats
#define S_MG   (S_M + 256)             // 14816: m - g, 256 floats
#define S_RED  (S_MG + 256)            // 15072: 1024 floats (mean partials / dcl partials)
#define SMEMF  (S_RED + 1024)          // 16096 floats = 64384 bytes

#define KEXP  0.3606737602222409f

typedef unsigned long long u64;

__device__ double       g_acc0;                 // dil
__device__ double       g_acc1;                 // dcl
__device__ unsigned int g_done;
__device__ float4       scr_dcl[GRID1 * 56];    // per (b,ch): 56 row partials
__device__ float4       scr_dil[GRID1 * 2];     // per (b,ch): 2 warp partials

__device__ __forceinline__ float ex2f(float x) {
    float r; asm("ex2.approx.ftz.f32 %0, %1;" : "=f"(r) : "f"(x)); return r;
}
__device__ __forceinline__ u64 f2_add(u64 a, u64 b) {
    u64 r; asm("add.rn.f32x2 %0, %1, %2;" : "=l"(r) : "l"(a), "l"(b)); return r;
}
__device__ __forceinline__ u64 f2_mul(u64 a, u64 b) {
    u64 r; asm("mul.rn.f32x2 %0, %1, %2;" : "=l"(r) : "l"(a), "l"(b)); return r;
}
__device__ __forceinline__ u64 f2_fma(u64 a, u64 b, u64 c) {
    u64 r; asm("fma.rn.f32x2 %0, %1, %2, %3;" : "=l"(r) : "l"(a), "l"(b), "l"(c)); return r;
}
__device__ __forceinline__ void f2_unpack(u64 v, float& lo, float& hi) {
    asm("mov.b64 {%0, %1}, %2;" : "=f"(lo), "=f"(hi) : "l"(v));
}
__device__ __forceinline__ u64 f2_pack(float lo, float hi) {
    u64 r; asm("mov.b64 %0, {%1, %2};" : "=l"(r) : "f"(lo), "f"(hi)); return r;
}

#define F2_NEG1 0xBF800000BF800000ULL
#define F2_KK   0x3EB8AA3B3EB8AA3BULL   /* (KEXP, KEXP) */
#define F2_I56  0x3C9249253C924925ULL   /* (1/56, 1/56) */

// ============================================================================
// k1: single pass over ebp. Block = (b, chunk).
// A: load 56 rows -> smem, mean in-flight. Mid: m, mg, dil partials.
// C: thread=(row,subchunk) dcl partials -> smem; 56 threads fold -> 56 float4.
// ============================================================================
__global__ void __launch_bounds__(256, 3) k1(const float* __restrict__ ebp,
                                             const float* __restrict__ ebg) {
    extern __shared__ float sm[];
    int b  = blockIdx.x >> 3;
    int ch = blockIdx.x & 7;
    int tid = threadIdx.x;

    if (blockIdx.x == 0 && tid == 0) { g_acc0 = 0.0; g_acc1 = 0.0; g_done = 0u; }

    // ---- Phase A: load + mean ----
    int rg = tid >> 6;          // row group 0..3
    int c4 = tid & 63;          // float4 index within chunk
    const ulonglong2* eb = (const ulonglong2*)ebp;
    size_t coff = (size_t)ch * C4 + c4;
    u64 aLo = 0, aHi = 0;
#pragma unroll 14
    for (int i = 0; i < 14; i++) {
        int p = i * 4 + rg;
        ulonglong2 v = eb[(size_t)(p * BATCH + b) * 512 + coff];
        *(ulonglong2*)&sm[S_P + p * RPAD + c4 * 4] = v;
        aLo = f2_add(aLo, v.x);
        aHi = f2_add(aHi, v.y);
    }
    *(ulonglong2*)&sm[S_RED + rg * 256 + c4 * 4] = make_ulonglong2(aLo, aHi);
    __syncthreads();

    // ---- Mid: finalize mean, mg, dil partials (threads 0..63) ----
    if (tid < 64) {
        ulonglong2 r0 = *(ulonglong2*)&sm[S_RED + 0 * 256 + tid * 4];
        ulonglong2 r1 = *(ulonglong2*)&sm[S_RED + 1 * 256 + tid * 4];
        ulonglong2 r2 = *(ulonglong2*)&sm[S_RED + 2 * 256 + tid * 4];
        ulonglong2 r3 = *(ulonglong2*)&sm[S_RED + 3 * 256 + tid * 4];
        u64 mLo = f2_mul(f2_add(f2_add(r0.x, r1.x), f2_add(r2.x, r3.x)), F2_I56);
        u64 mHi = f2_mul(f2_add(f2_add(r0.y, r1.y), f2_add(r2.y, r3.y)), F2_I56);
        ulonglong2 g = ((const ulonglong2*)ebg)[(size_t)b * 512 + coff];
        u64 mgLo = f2_fma(g.x, F2_NEG1, mLo);
        u64 mgHi = f2_fma(g.y, F2_NEG1, mHi);
        *(ulonglong2*)&sm[S_M  + tid * 4] = make_ulonglong2(mLo, mHi);
        *(ulonglong2*)&sm[S_MG + tid * 4] = make_ulonglong2(mgLo, mgHi);

        float m0, m1, m2, m3, g0, g1, g2, g3, u0, u1, u2, u3;
        f2_unpack(mLo, m0, m1); f2_unpack(mHi, m2, m3);
        f2_unpack(g.x, g0, g1); f2_unpack(g.y, g2, g3);
        f2_unpack(mgLo, u0, u1); f2_unpack(mgHi, u2, u3);
        float se_g = 0.f, se_m = 0.f, su_g = 0.f, su_m = 0.f;
#define DIL1(gg, mm, uu) { float eg = ex2f(gg * KEXP);          \
                           float em = ex2f(mm * KEXP);          \
                           se_g += eg; se_m += em;              \
                           su_g = fmaf(eg, uu, su_g);           \
                           su_m = fmaf(em, uu, su_m); }
        DIL1(g0, m0, u0) DIL1(g1, m1, u1) DIL1(g2, m2, u2) DIL1(g3, m3, u3)
#undef DIL1
#pragma unroll
        for (int off = 16; off; off >>= 1) {
            se_g += __shfl_xor_sync(0xffffffffu, se_g, off);
            se_m += __shfl_xor_sync(0xffffffffu, se_m, off);
            su_g += __shfl_xor_sync(0xffffffffu, su_g, off);
            su_m += __shfl_xor_sync(0xffffffffu, su_m, off);
        }
        if ((tid & 31) == 0)
            scr_dil[blockIdx.x * 2 + (tid >> 5)] =
                make_float4(se_g, se_m, su_g, su_m);
    }
    __syncthreads();

    // ---- Phase C: per-thread dcl partials -> smem ----
    int s = tid / 56;                  // subchunk 0..3 (tid>=224 idle)
    int r = tid - s * 56;              // row 0..55
    if (s < 4) {
        int j0 = s * 16;
        u64 seX = 0, seY = 0, suX = 0, suY = 0;
#pragma unroll 16
        for (int j = 0; j < 16; j++) {
            ulonglong2 P  = *(ulonglong2*)&sm[S_P  + r * RPAD + (j0 + j) * 4];
            ulonglong2 M  = *(ulonglong2*)&sm[S_M  + (j0 + j) * 4];
            ulonglong2 MG = *(ulonglong2*)&sm[S_MG + (j0 + j) * 4];
#define DCLP(pp, mm, gm) {                                       \
            u64 db = f2_fma(pp, F2_NEG1, mm);    /* m - p */     \
            u64 dg = f2_fma(gm, F2_NEG1, db);    /* g - p */     \
            u64 w  = f2_add(db, dg);                             \
            u64 u  = f2_mul(gm, w);                              \
            u64 ax = f2_mul(f2_mul(dg, dg), F2_KK);              \
            u64 ay = f2_mul(f2_mul(db, db), F2_KK);              \
            float a0, a1, b0, b1;                                \
            f2_unpack(ax, a0, a1); f2_unpack(ay, b0, b1);        \
            u64 ex = f2_pack(ex2f(a0), ex2f(a1));                \
            u64 ey = f2_pack(ex2f(b0), ex2f(b1));                \
            seX = f2_add(seX, ex); seY = f2_add(seY, ey);        \
            suX = f2_fma(ex, u, suX); suY = f2_fma(ey, u, suY); }
            DCLP(P.x, M.x, MG.x)
            DCLP(P.y, M.y, MG.y)
#undef DCLP
        }
        float x0, x1, y0, y1, z0, z1, w0, w1;
        f2_unpack(seX, x0, x1); f2_unpack(seY, y0, y1);
        f2_unpack(suX, z0, z1); f2_unpack(suY, w0, w1);
        *(float4*)&sm[S_RED + (s * 56 + r) * 4] =
            make_float4(x0 + x1, y0 + y1, z0 + z1, w0 + w1);
    }
    __syncthreads();

    // ---- fold 4 subchunks -> 1 float4 per row, write coalesced ----
    if (tid < 56) {
        float4 a = *(float4*)&sm[S_RED + (0 * 56 + tid) * 4];
        float4 c = *(float4*)&sm[S_RED + (1 * 56 + tid) * 4];
        float4 d = *(float4*)&sm[S_RED + (2 * 56 + tid) * 4];
        float4 e = *(float4*)&sm[S_RED + (3 * 56 + tid) * 4];
        scr_dcl[blockIdx.x * 56 + tid] =
            make_float4(a.x + c.x + d.x + e.x, a.y + c.y + d.y + e.y,
                        a.z + c.z + d.z + e.z, a.w + c.w + d.w + e.w);
    }
}

// ============================================================================
// k2: 256 blocks, one per b. Threads 0..55: combine 8 chunk-partials per row,
// divide, block-reduce -> dcl atomic. Warp 7: dil combine -> dil atomic.
// Last block writes out[0], out[1].
// ============================================================================
__global__ void __launch_bounds__(256) k2(float* __restrict__ out) {
    __shared__ float sdcl[56];
    __shared__ int s_last;
    int b = blockIdx.x;
    int tid = threadIdx.x, lane = tid & 31;

    if (tid < 56) {
        float4 a = make_float4(0.f, 0.f, 0.f, 0.f);
#pragma unroll 8
        for (int ch = 0; ch < 8; ch++) {
            float4 v = scr_dcl[b * 448 + ch * 56 + tid];
            a.x += v.x; a.y += v.y; a.z += v.z; a.w += v.w;
        }
        sdcl[tid] = a.w / a.y - a.z / a.x;
    }
    if (tid >= 224) {                   // warp 7: dil
        float4 v = (lane < 16) ? scr_dil[b * 16 + lane]
                               : make_float4(0.f, 0.f, 0.f, 0.f);
#pragma unroll
        for (int off = 8; off; off >>= 1) {
            v.x += __shfl_xor_sync(0xffffffffu, v.x, off);
            v.y += __shfl_xor_sync(0xffffffffu, v.y, off);
            v.z += __shfl_xor_sync(0xffffffffu, v.z, off);
            v.w += __shfl_xor_sync(0xffffffffu, v.w, off);
        }
        if (lane == 0)
            atomicAdd(&g_acc0, (double)(v.w / v.y - v.z / v.x));
    }
    __syncthreads();
    if (tid < 32) {
        float s = ((lane < 56) ? sdcl[lane] : 0.f) +
                  ((lane + 32 < 56) ? sdcl[lane + 32] : 0.f);
#pragma unroll
        for (int off = 16; off; off >>= 1)
            s += __shfl_xor_sync(0xffffffffu, s, off);
        if (lane == 0) atomicAdd(&g_acc1, (double)s);
    }

    __threadfence();
    __syncthreads();
    if (tid == 0) {
        unsigned prev = atomicAdd(&g_done, 1u);
        s_last = (prev == gridDim.x - 1) ? 1 : 0;
    }
    __syncthreads();
    if (s_last && tid == 0) {
        __threadfence();
        double a0 = *(volatile double*)&g_acc0;
        double a1 = *(volatile double*)&g_acc1;
        out[0] = (float)(a0 * (4.0 / (double)DIM));
        out[1] = (float)(a1 * (4.0 / ((double)DIM * (double)PNUM)));
    }
}

extern "C" void kernel_launch(void* const* d_in, const int* in_sizes, int n_in,
                              void* d_out, int out_size) {
    const float* ebg = (const float*)d_in[0];
    const float* ebp = (const float*)d_in[1];
    (void)in_sizes; (void)n_in; (void)out_size;

    cudaFuncSetAttribute(k1, cudaFuncAttributeMaxDynamicSharedMemorySize,
                         SMEMF * sizeof(float));
    k1<<<GRID1, 256, SMEMF * sizeof(float)>>>(ebp, ebg);
    k2<<<BATCH, 256>>>((float*)d_out);
}